// round 8
// baseline (speedup 1.0000x reference)
#include <cuda_runtime.h>
#include <float.h>
#include <cstdint>

#define QD 8192   // QUANT_DIM
#define ED 512    // EMBED_DIM
#define NT 8192   // N_TOKENS
#define CAP 256   // candidate capacity (overflow -> exact serial fallback)

// Scratch: weight.T [QD, ED] = 16 MB. Static __device__ global (no alloc).
__device__ float g_wT[(size_t)QD * ED];

// ---------------------------------------------------------------------------
// Kernel 1: tiled transpose weight[ED, QD] -> g_wT[QD, ED]
// ---------------------------------------------------------------------------
__global__ void transpose_kernel(const float* __restrict__ w) {
    __shared__ float tile[32][33];
    int qx = blockIdx.x * 32 + threadIdx.x;
    int ey = blockIdx.y * 32 + threadIdx.y;
#pragma unroll
    for (int j = 0; j < 32; j += 8)
        tile[threadIdx.y + j][threadIdx.x] = w[(size_t)(ey + j) * QD + qx];
    __syncthreads();
    int ex = blockIdx.y * 32 + threadIdx.x;
    int qy = blockIdx.x * 32 + threadIdx.y;
#pragma unroll
    for (int j = 0; j < 32; j += 8)
        g_wT[(size_t)(qy + j) * ED + ex] = tile[threadIdx.x][threadIdx.y + j];
}

// Strict total order lex(value desc, index asc) — matches jax.lax.top_k ties.
__device__ __forceinline__ bool lexgt(float av, int ai, float bv, int bi) {
    return (av > bv) || (av == bv && ai < bi);
}

__device__ __forceinline__ uint32_t smem_u32(const void* p) {
    uint32_t a;
    asm("{ .reg .u64 t; cvta.to.shared.u64 t, %1; cvt.u32.u64 %0, t; }"
        : "=r"(a) : "l"(p));
    return a;
}

// ---------------------------------------------------------------------------
// Kernel 2: block-per-token. Whole 32KB row streamed to smem with ONE
// cp.async.bulk (engine-side MLP; no per-warp latency exposure), then
// threshold top-8 + gather, all sourced from smem.
// ---------------------------------------------------------------------------
__global__ __launch_bounds__(256) void topk_gather_kernel(
    const float* __restrict__ x, float* __restrict__ out) {
    const int n = blockIdx.x;
    const int t = threadIdx.x;

    __shared__ __align__(128) float s_buf[QD];      // 32 KB row buffer
    __shared__ float s_max[256];
    __shared__ float s_cv[CAP];
    __shared__ int   s_ci[CAP];
    __shared__ int   s_cnt;
    __shared__ float s_T8;
    __shared__ int   s_fin[8];
    __shared__ __align__(8) unsigned long long s_mbar;

    const uint32_t mbar = smem_u32(&s_mbar);
    const uint32_t sbuf = smem_u32(s_buf);

    if (t == 0) {
        s_cnt = 0;
        asm volatile("mbarrier.init.shared.b64 [%0], 1;" :: "r"(mbar) : "memory");
    }
    __syncthreads();

    if (t == 0) {
        asm volatile("mbarrier.arrive.expect_tx.shared.b64 _, [%0], %1;"
                     :: "r"(mbar), "r"((uint32_t)(QD * 4)) : "memory");
        asm volatile(
            "cp.async.bulk.shared::cluster.global.mbarrier::complete_tx::bytes "
            "[%0], [%1], %2, [%3];"
            :: "r"(sbuf), "l"(x + (size_t)n * QD), "r"((uint32_t)(QD * 4)),
               "r"(mbar) : "memory");
    }

    // All threads wait for the row (acquire orders the async writes).
    {
        uint32_t done;
        do {
            asm volatile(
                "{ .reg .pred p;\n\t"
                "mbarrier.try_wait.parity.acquire.cta.shared::cta.b64 p, [%1], 0, 0x989680;\n\t"
                "selp.b32 %0, 1, 0, p; }"
                : "=r"(done) : "r"(mbar) : "memory");
        } while (!done);
    }

    // ---- Phase 1: per-thread max over 32 smem elems (lane-contiguous,
    // conflict-free LDS.128; pure FMNMX; keep 4 group maxima for rescan).
    const float4* b4 = reinterpret_cast<const float4*>(s_buf);
    float gmax[4];
#pragma unroll
    for (int c = 0; c < 4; c++) {
        float4 a = b4[(2 * c) * 256 + t];
        float4 b = b4[(2 * c + 1) * 256 + t];
        float m0 = fmaxf(fmaxf(a.x, a.y), fmaxf(a.z, a.w));
        float m1 = fmaxf(fmaxf(b.x, b.y), fmaxf(b.z, b.w));
        gmax[c] = fmaxf(m0, m1);
    }
    float tmax = fmaxf(fmaxf(gmax[0], gmax[1]), fmaxf(gmax[2], gmax[3]));
    s_max[t] = tmax;
    __syncthreads();

    // ---- Phase 2 (warp 0): T8 = 8th-largest of the 256 thread maxima.
    // The 8 threads owning the top-8 maxima hold 8 distinct elements >= T8,
    // so every true top-8 element passes v >= T8.
    if (t < 32) {
        float m[8];
#pragma unroll
        for (int j = 0; j < 8; j++) m[j] = s_max[j * 32 + t];
#define VCE(i, j) { float lo = fminf(m[i], m[j]); m[i] = fmaxf(m[i], m[j]); m[j] = lo; }
        VCE(0, 1) VCE(2, 3) VCE(4, 5) VCE(6, 7)
        VCE(0, 2) VCE(1, 3) VCE(4, 6) VCE(5, 7)
        VCE(1, 2) VCE(5, 6)
        VCE(0, 4) VCE(1, 5) VCE(2, 6) VCE(3, 7)
        VCE(2, 4) VCE(3, 5)
        VCE(1, 2) VCE(3, 4) VCE(5, 6)
#undef VCE
#pragma unroll
        for (int s = 1; s < 32; s <<= 1) {
            float p[8];
#pragma unroll
            for (int r = 0; r < 8; r++) p[r] = __shfl_xor_sync(0xffffffffu, m[r], s);
            float L[8];
#pragma unroll
            for (int r = 0; r < 8; r++) L[r] = fmaxf(m[r], p[7 - r]);
#define VCE2(i, j) { float lo = fminf(L[i], L[j]); L[i] = fmaxf(L[i], L[j]); L[j] = lo; }
            VCE2(0, 4) VCE2(1, 5) VCE2(2, 6) VCE2(3, 7)
            VCE2(0, 2) VCE2(1, 3) VCE2(4, 6) VCE2(5, 7)
            VCE2(0, 1) VCE2(2, 3) VCE2(4, 5) VCE2(6, 7)
#undef VCE2
#pragma unroll
            for (int r = 0; r < 8; r++) m[r] = L[r];
        }
        if (t == 0) s_T8 = m[7];
    }
    __syncthreads();
    const float T8 = s_T8;

    // ---- Phase 3: rescan triggered groups from smem (cheap LDS re-reads).
    if (tmax >= T8) {
#pragma unroll
        for (int c = 0; c < 4; c++) {
            if (gmax[c] >= T8) {
                float4 a = b4[(2 * c) * 256 + t];
                float4 b = b4[(2 * c + 1) * 256 + t];
                int ia = 4 * ((2 * c) * 256 + t);
                int ib = 4 * ((2 * c + 1) * 256 + t);
                float va[8] = {a.x, a.y, a.z, a.w, b.x, b.y, b.z, b.w};
                int   id[8] = {ia, ia + 1, ia + 2, ia + 3, ib, ib + 1, ib + 2, ib + 3};
#pragma unroll
                for (int j = 0; j < 8; j++) {
                    if (va[j] >= T8) {
                        int pos = atomicAdd(&s_cnt, 1);
                        if (pos < CAP) { s_cv[pos] = va[j]; s_ci[pos] = id[j]; }
                    }
                }
            }
        }
    }
    __syncthreads();

    const int C = s_cnt;  // >= 8 guaranteed
    if (C <= CAP) {
        // ---- Phase 4 (warp 0): exact lex top-8 over the candidate list.
        if (t < 32) {
            float tv[8]; int ti[8];
#pragma unroll
            for (int r = 0; r < 8; r++) { tv[r] = -FLT_MAX; ti[r] = 0x7FFFFFFF; }
            for (int i = t; i < C; i += 32) {
                float v = s_cv[i]; int id = s_ci[i];
                if (lexgt(v, id, tv[7], ti[7])) {
                    tv[7] = v; ti[7] = id;
#pragma unroll
                    for (int p = 7; p > 0; p--) {
                        if (lexgt(tv[p], ti[p], tv[p - 1], ti[p - 1])) {
                            float fv = tv[p]; tv[p] = tv[p - 1]; tv[p - 1] = fv;
                            int   fi = ti[p]; ti[p] = ti[p - 1]; ti[p - 1] = fi;
                        }
                    }
                }
            }
#pragma unroll
            for (int s = 1; s < 32; s <<= 1) {
                float pv[8]; int pi[8];
#pragma unroll
                for (int r = 0; r < 8; r++) {
                    pv[r] = __shfl_xor_sync(0xffffffffu, tv[r], s);
                    pi[r] = __shfl_xor_sync(0xffffffffu, ti[r], s);
                }
                float L[8]; int Li[8];
#pragma unroll
                for (int r = 0; r < 8; r++) {
                    bool p = lexgt(tv[r], ti[r], pv[7 - r], pi[7 - r]);
                    L[r]  = p ? tv[r] : pv[7 - r];
                    Li[r] = p ? ti[r] : pi[7 - r];
                }
#define LCE(i, j)                                                       \
                {                                                       \
                    if (lexgt(L[j], Li[j], L[i], Li[i])) {              \
                        float fv = L[i]; L[i] = L[j]; L[j] = fv;        \
                        int   fi = Li[i]; Li[i] = Li[j]; Li[j] = fi;    \
                    }                                                   \
                }
                LCE(0, 4) LCE(1, 5) LCE(2, 6) LCE(3, 7)
                LCE(0, 2) LCE(1, 3) LCE(4, 6) LCE(5, 7)
                LCE(0, 1) LCE(2, 3) LCE(4, 5) LCE(6, 7)
#undef LCE
#pragma unroll
                for (int r = 0; r < 8; r++) { tv[r] = L[r]; ti[r] = Li[r]; }
            }
            if (t < 8) s_fin[t] = ti[t];
        }
    } else {
        // Overflow fallback: exact serial scan from smem (never on this data).
        if (t == 0) {
            float tv[8]; int ti[8];
#pragma unroll
            for (int r = 0; r < 8; r++) { tv[r] = -FLT_MAX; ti[r] = 0x7FFFFFFF; }
            for (int i = 0; i < QD; i++) {
                float v = s_buf[i];
                if (lexgt(v, i, tv[7], ti[7])) {
                    tv[7] = v; ti[7] = i;
#pragma unroll
                    for (int p = 7; p > 0; p--) {
                        if (lexgt(tv[p], ti[p], tv[p - 1], ti[p - 1])) {
                            float fv = tv[p]; tv[p] = tv[p - 1]; tv[p - 1] = fv;
                            int   fi = ti[p]; ti[p] = ti[p - 1]; ti[p - 1] = fi;
                        }
                    }
                }
            }
#pragma unroll
            for (int r = 0; r < 8; r++) s_fin[r] = ti[r];
        }
    }
    __syncthreads();

    // ---- Phase 5: out[n, :] = sum_{j<8} wT[idx_j, :] (coalesced float2).
    // List is value-descending == jax's summation order.
    int idx[8];
#pragma unroll
    for (int r = 0; r < 8; r++) idx[r] = s_fin[r];

    const float2* wT2 = reinterpret_cast<const float2*>(g_wT);
    float2 acc = make_float2(0.f, 0.f);
#pragma unroll
    for (int r = 0; r < 8; r++) {
        float2 w = wT2[(size_t)idx[r] * (ED / 2) + t];
        acc.x += w.x;
        acc.y += w.y;
    }
    reinterpret_cast<float2*>(out)[(size_t)n * (ED / 2) + t] = acc;
}

// ---------------------------------------------------------------------------
extern "C" void kernel_launch(void* const* d_in, const int* in_sizes, int n_in,
                              void* d_out, int out_size) {
    const float* x = (const float*)d_in[0];   // [NT, QD] f32
    const float* w = (const float*)d_in[1];   // [ED, QD] f32
    float* out = (float*)d_out;               // [NT, ED] f32

    dim3 tb(32, 8);
    dim3 tg(QD / 32, ED / 32);
    transpose_kernel<<<tg, tb>>>(w);
    topk_gather_kernel<<<NT, 256>>>(x, out);
}